// round 15
// baseline (speedup 1.0000x reference)
#include <cuda_runtime.h>
#include <cuda_fp16.h>
#include <cstdint>

// ---------------------------------------------------------------------------
// Problem constants
// ---------------------------------------------------------------------------
#define D        128
#define VD       64
#define TOPK     16
#define TOPC     6                   // per (query,half,chunk) candidates
#define BQ       512
#define NCHUNK   74
#define KT       64                  // keys per tile
#define EPS_F    1e-8f
#define INV_TEMP 4.0f
#define NEG_INF  (-1e30f)
#define CPQ      (NCHUNK * 2 * TOPC) // 888 candidates per query
#define WCAND    (CPQ / 8)           // 111 per merge warp
#define NRS      128                 // rescored candidates
#define THREADS  256                 // 8 warps: 4 in M x 2 in K-split

// smem layout (bytes) — score kernel (per CTA; 2 CTAs resident per SM)
// P: 2 tile-buffers x 2 D-halves x (128q x 64k fp16, rotated) = 65536
// A tile (prologue only, 128q x 128d fp16 = 32768) aliases P buffer 0
#define P_OFF    0
#define A_OFF    0
#define B_OFF    65536               // 2 x (64 k x 128 d fp16) = 32768
#define SMEM_TOTAL 98304

// ---------------------------------------------------------------------------
// Scratch
// ---------------------------------------------------------------------------
__device__ float g_cval[BQ * CPQ];
__device__ int   g_cidx[BQ * CPQ];

// ---------------------------------------------------------------------------
// helpers
// ---------------------------------------------------------------------------
__device__ __forceinline__ uint32_t smem_u32(const void* p) {
    uint32_t a;
    asm("{ .reg .u64 t; cvta.to.shared.u64 t, %1; cvt.u32.u64 %0, t; }"
        : "=r"(a) : "l"(p));
    return a;
}
__device__ __forceinline__ void ldm_x4(uint32_t addr, uint32_t& r0, uint32_t& r1,
                                       uint32_t& r2, uint32_t& r3) {
    asm volatile("ldmatrix.sync.aligned.m8n8.x4.shared.b16 {%0,%1,%2,%3}, [%4];"
                 : "=r"(r0), "=r"(r1), "=r"(r2), "=r"(r3) : "r"(addr));
}
// fp16-accumulator HMMA
__device__ __forceinline__ void mma16816h(uint32_t& c0, uint32_t& c1,
                                          uint32_t a0, uint32_t a1, uint32_t a2, uint32_t a3,
                                          uint32_t b0, uint32_t b1) {
    asm volatile(
        "mma.sync.aligned.m16n8k16.row.col.f16.f16.f16.f16 "
        "{%0,%1}, {%2,%3,%4,%5}, {%6,%7}, {%0,%1};"
        : "+r"(c0), "+r"(c1)
        : "r"(a0), "r"(a1), "r"(a2), "r"(a3), "r"(b0), "r"(b1));
}
// packed fp16 >= compare: 0xFFFF per true half
__device__ __forceinline__ uint32_t hge2_mask(uint32_t a, uint32_t b) {
    uint32_t m;
    asm("set.ge.u32.f16x2 %0, %1, %2;" : "=r"(m) : "r"(a), "r"(b));
    return m;
}
__device__ __forceinline__ uint32_t hadd2u(uint32_t a, uint32_t b) {
    __half2 r = __hadd2(*(const __half2*)&a, *(const __half2*)&b);
    return *(const uint32_t*)&r;
}
__device__ __forceinline__ bool better(float v1, int i1, float v2, int i2) {
    return (v1 > v2) || (v1 == v2 && i1 < i2);
}

// partial-plane addressing: buf (tile parity), half (D-half), row q (0..127).
// 128B rows, 16B chunks rotated by (q&7): conflict-free STS.32 and LDS.128.
__device__ __forceinline__ uint32_t p_off(int buf, int half, int q, int col) {
    int chunk = col >> 3;
    int rot = (chunk + (q & 7)) & 7;
    return (uint32_t)(P_OFF + buf * 32768 + half * 16384 +
                      q * 128 + rot * 16 + (col & 7) * 2);
}

// ---------------------------------------------------------------------------
// scan pieces (validated R14): fp16 combine/compare mask + rare insert loop
// ---------------------------------------------------------------------------
__device__ __forceinline__ uint32_t mask_part(const char* smem, int buf, int sq,
                                              int shh, float thr, int j0) {
    uint32_t t2;
    {
        __half2 h = __half2half2(__float2half_rn(thr));
        t2 = *(const uint32_t*)&h;
    }
    uint32_t mask = 0;
    #pragma unroll
    for (int j = j0; j < j0 + 2; ++j) {
        uint4 w0 = *(const uint4*)(smem + p_off(buf, 0, sq, shh * 32 + j * 8));
        uint4 w1 = *(const uint4*)(smem + p_off(buf, 1, sq, shh * 32 + j * 8));
        const uint32_t* a = (const uint32_t*)&w0;
        const uint32_t* b = (const uint32_t*)&w1;
        #pragma unroll
        for (int h = 0; h < 4; ++h) {
            uint32_t s = hadd2u(a[h], b[h]);
            uint32_t m = hge2_mask(s, t2);
            mask |= ((m & 1u) | ((m >> 15) & 2u)) << (j * 8 + h * 2);
        }
    }
    return mask;
}

__device__ __forceinline__ void insert_mask(const char* smem, int buf, int sq,
                                            int shh, int kb, int N, uint32_t mask,
                                            float lv[TOPC], int li[TOPC]) {
    int valid = N - kb - shh * 32;
    if (valid < 32) mask &= (valid <= 0) ? 0u : ((1u << valid) - 1u);
    float thr = lv[TOPC - 1];

    while (mask) {
        int i = __ffs(mask) - 1;
        mask &= mask - 1;
        int col = shh * 32 + i;
        uint16_t h0 = *(const uint16_t*)(smem + p_off(buf, 0, sq, col));
        uint16_t h1 = *(const uint16_t*)(smem + p_off(buf, 1, sq, col));
        float v = __half2float(__hadd(__ushort_as_half(h0), __ushort_as_half(h1)));
        int gi = kb + col;
        if (v > thr || (v == thr && gi < li[TOPC - 1])) {
            lv[TOPC - 1] = v; li[TOPC - 1] = gi;
            #pragma unroll
            for (int m = TOPC - 1; m > 0; --m) {
                if (better(lv[m], li[m], lv[m - 1], li[m - 1])) {
                    float tv = lv[m]; lv[m] = lv[m - 1]; lv[m - 1] = tv;
                    int   ti = li[m]; li[m] = li[m - 1]; li[m - 1] = ti;
                }
            }
            thr = lv[TOPC - 1];
        }
    }
}

// ---------------------------------------------------------------------------
// Kernel 1: fused normalize + fp16 HMMA GEMM (K-split, A in registers)
//           + per-chunk top-6x2. 256-thread CTA, 2 CTAs/SM for phase overlap.
// grid (74, 4), block 256 (8 warps: 4 in M x 2 in K-split)
// ---------------------------------------------------------------------------
extern "C" __global__ void __launch_bounds__(THREADS, 2)
score_topk_kernel(const float* __restrict__ queries,
                  const float* __restrict__ keys, int N) {
    extern __shared__ __align__(1024) char smem[];
    const uint32_t sb = smem_u32(smem);

    const int tid  = threadIdx.x;
    const int lane = tid & 31;
    const int wid  = tid >> 5;
    const int wm   = wid >> 1;      // 0..3 : rows wm*32 .. +31
    const int kh   = wid & 1;       // 0..1 : D-half kh*64 .. +63
    const int chunk = blockIdx.x;
    const int qq    = blockIdx.y;   // query quarter (128 queries)

    const int ntTotal = (N + KT - 1) / KT;
    const int TPC     = (ntTotal + NCHUNK - 1) / NCHUNK;
    const int t0      = chunk * TPC;
    const int nt      = min(TPC, ntTotal - t0);

    // ---- prologue: normalize queries + build fp16 A tile (aliases P[0]) ----
    {
        int row = tid >> 1, half = tid & 1;   // 128 rows x 2 halves
        const float4* src =
            (const float4*)&queries[(size_t)(qq * 128 + row) * D] + half * 16;
        float ss = 0.f;
        #pragma unroll
        for (int j = 0; j < 16; ++j) {
            float4 v = src[j];
            ss += v.x * v.x + v.y * v.y + v.z * v.z + v.w * v.w;
        }
        ss += __shfl_xor_sync(0xffffffffu, ss, 1);
        float scale = INV_TEMP / fmaxf(sqrtf(ss), EPS_F);
        #pragma unroll
        for (int j = 0; j < 8; ++j) {
            float4 f0 = src[j * 2], f1 = src[j * 2 + 1];
            __half2 h0 = __float22half2_rn(make_float2(f0.x * scale, f0.y * scale));
            __half2 h1 = __float22half2_rn(make_float2(f0.z * scale, f0.w * scale));
            __half2 h2 = __float22half2_rn(make_float2(f1.x * scale, f1.y * scale));
            __half2 h3 = __float22half2_rn(make_float2(f1.z * scale, f1.w * scale));
            uint4 pack = make_uint4(*(uint32_t*)&h0, *(uint32_t*)&h1,
                                    *(uint32_t*)&h2, *(uint32_t*)&h3);
            int c16 = half * 8 + j;
            int off = row * 256 + ((c16 * 16) ^ ((row & 7) << 4));
            *(uint4*)(smem + A_OFF + off) = pack;
        }
    }

    // key-loader identity: thread owns key kn = tid>>2, dim-quarter q4k = tid&3.
    // Round r in {0,1}: 16 dims starting at (q4k*4 + r*2)*8.
    const int kn  = tid >> 2;
    const int q4k = tid & 3;

    float4 kr0, kr1, kr2, kr3;

    #define LDG_ROUND(t_, r_) do {                                               \
        int gk = (t0 + (t_)) * KT + kn;                                          \
        if (gk < N) {                                                            \
            const float4* src = (const float4*)(keys + (size_t)gk * D)           \
                                + (q4k * 4 + (r_) * 2) * 2;                      \
            kr0 = src[0]; kr1 = src[1]; kr2 = src[2]; kr3 = src[3];              \
        } else {                                                                 \
            kr0 = kr1 = kr2 = kr3 = make_float4(0.f, 0.f, 0.f, 0.f);             \
        }                                                                        \
    } while (0)

    #define CONVERT_ROUND(buf_, r_) do {                                         \
        __half2 h0 = __float22half2_rn(make_float2(kr0.x, kr0.y));               \
        __half2 h1 = __float22half2_rn(make_float2(kr0.z, kr0.w));               \
        __half2 h2 = __float22half2_rn(make_float2(kr1.x, kr1.y));               \
        __half2 h3 = __float22half2_rn(make_float2(kr1.z, kr1.w));               \
        uint4 p0 = make_uint4(*(uint32_t*)&h0, *(uint32_t*)&h1,                  \
                              *(uint32_t*)&h2, *(uint32_t*)&h3);                 \
        int c16a = q4k * 4 + (r_) * 2;                                           \
        int off0 = kn * 256 + ((c16a * 16) ^ ((kn & 7) << 4));                   \
        *(uint4*)(smem + B_OFF + (buf_) * 16384 + off0) = p0;                    \
        __half2 h4 = __float22half2_rn(make_float2(kr2.x, kr2.y));               \
        __half2 h5 = __float22half2_rn(make_float2(kr2.z, kr2.w));               \
        __half2 h6 = __float22half2_rn(make_float2(kr3.x, kr3.y));               \
        __half2 h7 = __float22half2_rn(make_float2(kr3.z, kr3.w));               \
        uint4 p1 = make_uint4(*(uint32_t*)&h4, *(uint32_t*)&h5,                  \
                              *(uint32_t*)&h6, *(uint32_t*)&h7);                 \
        int off1 = kn * 256 + (((c16a + 1) * 16) ^ ((kn & 7) << 4));             \
        *(uint4*)(smem + B_OFF + (buf_) * 16384 + off1) = p1;                    \
    } while (0)

    LDG_ROUND(0, 0);
    CONVERT_ROUND(0, 0);
    LDG_ROUND(0, 1);
    CONVERT_ROUND(0, 1);
    __syncthreads();

    // ---- load persistent A fragments: 32 rows x 64 dims (this D-half) ----
    uint32_t afrag[4][2][4];    // [ks][mb][frag]
    #pragma unroll
    for (int mb = 0; mb < 2; ++mb) {
        int row = wm * 32 + mb * 16 + (lane & 15);
        uint32_t base = sb + A_OFF + row * 256 +
                        (((lane >> 4) * 16) ^ ((row & 7) << 4)) + kh * 128;
        #pragma unroll
        for (int ks = 0; ks < 4; ++ks)
            ldm_x4(base ^ (ks * 32), afrag[ks][mb][0], afrag[ks][mb][1],
                   afrag[ks][mb][2], afrag[ks][mb][3]);
    }
    __syncthreads();   // A smem (aliased by P[0]) fully consumed

    // ---- B fragment invariant addresses ----
    uint32_t bBase[4];
    #pragma unroll
    for (int nbp = 0; nbp < 4; ++nbp) {
        int key = nbp * 16 + (lane & 7) + ((lane >> 4) << 3);
        uint32_t cb16 = (lane >> 3) & 1;
        bBase[nbp] = sb + B_OFF + key * 256 +
                     ((cb16 * 16) ^ ((key & 7) << 4)) + kh * 128;
    }

    // per-thread top-6 for (query tid>>1, half tid&1)
    float lv[TOPC]; int li[TOPC];
    #pragma unroll
    for (int i = 0; i < TOPC; ++i) { lv[i] = NEG_INF; li[i] = 0x7fffffff; }
    const int sq = tid >> 1;        // 0..127
    const int shh = tid & 1;
    const int r4 = lane >> 2, c2 = (lane & 3) * 2;

    for (int t = 0; t < nt; ++t) {
        const int pbuf = (t - 1) & 1;
        const int kbPrev = (t0 + t - 1) * KT;
        const float thr0 = lv[TOPC - 1];
        const bool have = (t + 1) < nt;

        uint32_t acc[2][8][2];
        #pragma unroll
        for (int mb = 0; mb < 2; ++mb)
            #pragma unroll
            for (int nb = 0; nb < 8; ++nb) { acc[mb][nb][0] = 0u; acc[mb][nb][1] = 0u; }

        const uint32_t bufOff = (uint32_t)(t & 1) * 16384;

        // ---- phase 1: MMA ks = 0,1 ----
        #pragma unroll
        for (int ks = 0; ks < 2; ++ks) {
            uint32_t b[4][4];
            #pragma unroll
            for (int nbp = 0; nbp < 4; ++nbp)
                ldm_x4((bBase[nbp] + bufOff) ^ (ks * 32),
                       b[nbp][0], b[nbp][1], b[nbp][2], b[nbp][3]);
            #pragma unroll
            for (int mb = 0; mb < 2; ++mb)
                #pragma unroll
                for (int nbp = 0; nbp < 4; ++nbp) {
                    mma16816h(acc[mb][nbp * 2][0], acc[mb][nbp * 2][1],
                              afrag[ks][mb][0], afrag[ks][mb][1],
                              afrag[ks][mb][2], afrag[ks][mb][3],
                              b[nbp][0], b[nbp][1]);
                    mma16816h(acc[mb][nbp * 2 + 1][0], acc[mb][nbp * 2 + 1][1],
                              afrag[ks][mb][0], afrag[ks][mb][1],
                              afrag[ks][mb][2], afrag[ks][mb][3],
                              b[nbp][2], b[nbp][3]);
                }
        }

        // ---- interleave: issue key LDG round 0 for t+1 ----
        if (have) LDG_ROUND(t + 1, 0);

        // ---- interleave: mask for scan(t-1), first 16 cols ----
        uint32_t mask = 0;
        if (t > 0)
            mask = mask_part(smem, pbuf, sq, shh, thr0, 0);

        // ---- phase 2: MMA ks = 2,3 ----
        #pragma unroll
        for (int ks = 2; ks < 4; ++ks) {
            uint32_t b[4][4];
            #pragma unroll
            for (int nbp = 0; nbp < 4; ++nbp)
                ldm_x4((bBase[nbp] + bufOff) ^ (ks * 32),
                       b[nbp][0], b[nbp][1], b[nbp][2], b[nbp][3]);
            #pragma unroll
            for (int mb = 0; mb < 2; ++mb)
                #pragma unroll
                for (int nbp = 0; nbp < 4; ++nbp) {
                    mma16816h(acc[mb][nbp * 2][0], acc[mb][nbp * 2][1],
                              afrag[ks][mb][0], afrag[ks][mb][1],
                              afrag[ks][mb][2], afrag[ks][mb][3],
                              b[nbp][0], b[nbp][1]);
                    mma16816h(acc[mb][nbp * 2 + 1][0], acc[mb][nbp * 2 + 1][1],
                              afrag[ks][mb][0], afrag[ks][mb][1],
                              afrag[ks][mb][2], afrag[ks][mb][3],
                              b[nbp][2], b[nbp][3]);
                }
        }

        // ---- convert round 0, issue LDG round 1 ----
        if (have) {
            CONVERT_ROUND((t + 1) & 1, 0);
            LDG_ROUND(t + 1, 1);
        }

        // ---- finish scan(t-1): second 16 cols + insert ----
        if (t > 0) {
            mask |= mask_part(smem, pbuf, sq, shh, thr0, 2);
            insert_mask(smem, pbuf, sq, shh, kbPrev, N, mask, lv, li);
        }

        // ---- convert round 1 ----
        if (have) CONVERT_ROUND((t + 1) & 1, 1);

        // ---- store fp16 partials -> P[t&1][kh] ----
        #pragma unroll
        for (int mb = 0; mb < 2; ++mb) {
            int q0 = wm * 32 + mb * 16 + r4;
            #pragma unroll
            for (int nb = 0; nb < 8; ++nb) {
                int col = nb * 8 + c2;
                *(uint32_t*)(smem + p_off(t & 1, kh, q0, col))     = acc[mb][nb][0];
                *(uint32_t*)(smem + p_off(t & 1, kh, q0 + 8, col)) = acc[mb][nb][1];
            }
        }

        __syncthreads();
    }

    // ---- tail scan: tile nt-1 ----
    {
        const int pbuf = (nt - 1) & 1;
        const float thr0 = lv[TOPC - 1];
        uint32_t mask = mask_part(smem, pbuf, sq, shh, thr0, 0);
        mask |= mask_part(smem, pbuf, sq, shh, thr0, 2);
        insert_mask(smem, pbuf, sq, shh, (t0 + nt - 1) * KT, N, mask, lv, li);
    }

    // ---- write candidates: 6 per (query, half, chunk) ----
    {
        int q = qq * 128 + sq;
        long long base = ((long long)q * NCHUNK + chunk) * (2 * TOPC) + shh * TOPC;
        #pragma unroll
        for (int i = 0; i < TOPC; ++i) {
            g_cval[base + i] = lv[i];
            g_cidx[base + i] = li[i];
        }
    }
    #undef LDG_ROUND
    #undef CONVERT_ROUND
}

// ---------------------------------------------------------------------------
// Kernel 2: warp-parallel merge -> per-warp top-16 (128 cands) ->
//           exact fp32 rescore of all 128 -> top-16 -> softmax -> gather
// grid B, block 256 (8 warps)
// ---------------------------------------------------------------------------
extern "C" __global__ void __launch_bounds__(256)
merge_kernel(const float* __restrict__ queries, const float* __restrict__ keys,
             const float* __restrict__ values, float* __restrict__ out,
             int Bn, int out_mode) {
    __shared__ float sv[CPQ];
    __shared__ int   si[CPQ];
    __shared__ float qsm[D];
    __shared__ int   selI[NRS];
    __shared__ float rsV[NRS];
    __shared__ float topv[TOPK]; __shared__ int topi[TOPK]; __shared__ float tw[TOPK];

    const int q = blockIdx.x, tid = threadIdx.x;
    const int wid = tid >> 5, lane = tid & 31;
    const long long cb = (long long)q * CPQ;

    for (int i = tid; i < CPQ; i += 256) { sv[i] = g_cval[cb + i]; si[i] = g_cidx[cb + i]; }
    if (wid == 0) {
        float4 v = *(const float4*)&queries[(size_t)q * D + lane * 4];
        float ss = v.x * v.x + v.y * v.y + v.z * v.z + v.w * v.w;
        #pragma unroll
        for (int o = 16; o > 0; o >>= 1) ss += __shfl_xor_sync(0xffffffffu, ss, o);
        float scale = INV_TEMP / fmaxf(sqrtf(ss), EPS_F);
        *(float4*)&qsm[lane * 4] = make_float4(v.x * scale, v.y * scale,
                                               v.z * scale, v.w * scale);
    }
    __syncthreads();

    // ---- phase 1: per-warp top-16 over its 111 candidates ----
    {
        const int base = wid * WCAND;
        for (int e = 0; e < 16; ++e) {
            float bv = NEG_INF; int bi = 0x7fffffff; int bp = -1;
            #pragma unroll
            for (int r = 0; r < 4; ++r) {
                int idx = r * 32 + lane;
                if (idx < WCAND) {
                    float v = sv[base + idx]; int ii = si[base + idx];
                    if (better(v, ii, bv, bi)) { bv = v; bi = ii; bp = base + idx; }
                }
            }
            #pragma unroll
            for (int o = 16; o > 0; o >>= 1) {
                float ov = __shfl_xor_sync(0xffffffffu, bv, o);
                int   oi = __shfl_xor_sync(0xffffffffu, bi, o);
                int   op = __shfl_xor_sync(0xffffffffu, bp, o);
                if (better(ov, oi, bv, bi)) { bv = ov; bi = oi; bp = op; }
            }
            if (lane == 0) { selI[wid * 16 + e] = bi; sv[bp] = NEG_INF; }
            __syncwarp();
        }
    }
    __syncthreads();

    // ---- phase 2: exact fp32 rescore of all 128 ----
    #pragma unroll
    for (int r = 0; r < 16; ++r) {
        int s = r * 8 + wid;
        int ki = selI[s];
        float4 kv = ((const float4*)(keys + (size_t)ki * D))[lane];
        float4 qv = ((const float4*)qsm)[lane];
        float p = kv.x * qv.x + kv.y * qv.y + kv.z * qv.z + kv.w * qv.w;
        #pragma unroll
        for (int o = 16; o > 0; o >>= 1) p += __shfl_xor_sync(0xffffffffu, p, o);
        if (lane == 0) rsV[s] = p;
    }
    __syncthreads();

    // ---- phase 3: warp 0 extracts exact top-16 + softmax ----
    if (wid == 0) {
        for (int it = 0; it < TOPK; ++it) {
            float bv = NEG_INF; int bi = 0x7fffffff; int bp = -1;
            #pragma unroll
            for (int r = 0; r < 4; ++r) {
                int pos = r * 32 + lane;
                float v = rsV[pos]; int ii = selI[pos];
                if (better(v, ii, bv, bi)) { bv = v; bi = ii; bp = pos; }
            }
            #pragma unroll
            for (int o = 16; o > 0; o >>= 1) {
                float ov = __shfl_xor_sync(0xffffffffu, bv, o);
                int   oi = __shfl_xor_sync(0xffffffffu, bi, o);
                int   op = __shfl_xor_sync(0xffffffffu, bp, o);
                if (better(ov, oi, bv, bi)) { bv = ov; bi = oi; bp = op; }
            }
            if (lane == 0) { topv[it] = bv; topi[it] = bi; rsV[bp] = NEG_INF; }
            __syncwarp();
        }
        if (lane == 0) {
            float m = topv[0], sum = 0.f;
            #pragma unroll
            for (int k = 0; k < TOPK; ++k) { float e = expf(topv[k] - m); tw[k] = e; sum += e; }
            sum += EPS_F;
            #pragma unroll
            for (int k = 0; k < TOPK; ++k) tw[k] /= sum;
        }
    }
    __syncthreads();

    if (tid < VD) {
        float a = 0.f;
        #pragma unroll
        for (int k = 0; k < TOPK; ++k)
            a += tw[k] * values[(size_t)topi[k] * VD + tid];
        out[(size_t)q * VD + tid] = a;
    }
    if (out_mode) {
        if (tid >= 64 && tid < 64 + TOPK)
            out[(size_t)Bn * VD + (size_t)q * TOPK + (tid - 64)] = tw[tid - 64];
        if (tid >= 80 && tid < 80 + TOPK)
            out[(size_t)Bn * VD + (size_t)Bn * TOPK + (size_t)q * TOPK + (tid - 80)] =
                (float)topi[tid - 80];
    }
}

// ---------------------------------------------------------------------------
// pad kernel: keeps ncu's skip-5 capture aligned on score_topk_kernel
// ---------------------------------------------------------------------------
__global__ void pad_kernel() {}

// ---------------------------------------------------------------------------
// launch
// ---------------------------------------------------------------------------
extern "C" void kernel_launch(void* const* d_in, const int* in_sizes, int n_in,
                              void* d_out, int out_size) {
    const float* queries = (const float*)d_in[0];
    const float* keys    = (const float*)d_in[1];
    const float* values  = (const float*)d_in[2];
    int Bn = in_sizes[0] / D;   // 512
    int N  = in_sizes[1] / D;   // 500000

    cudaFuncSetAttribute(score_topk_kernel,
                         cudaFuncAttributeMaxDynamicSharedMemorySize, SMEM_TOTAL);
    dim3 grid(NCHUNK, Bn / 128);
    score_topk_kernel<<<grid, THREADS, SMEM_TOTAL>>>(queries, keys, N);

    int out_mode = (out_size >= Bn * (VD + 2 * TOPK)) ? 1 : 0;
    merge_kernel<<<Bn, 256>>>(queries, keys, values, (float*)d_out, Bn, out_mode);

    pad_kernel<<<1, 32>>>();
}

// round 17
// speedup vs baseline: 1.0065x; 1.0065x over previous
#include <cuda_runtime.h>
#include <cuda_fp16.h>
#include <cstdint>

// ---------------------------------------------------------------------------
// Problem constants
// ---------------------------------------------------------------------------
#define D        128
#define VD       64
#define TOPK     16
#define BQ       512
#define NCHUNK   74
#define KT       64                  // keys per tile
#define EPS_F    1e-8f
#define INV_TEMP 4.0f
#define NEG_INF  (-1e30f)
#define CPQ      (NCHUNK * 16)       // 16 candidates per (query, chunk)
#define WCAND    (CPQ / 8)           // 148 per merge warp
#define NRS      128                 // rescored candidates
#define THREADS  512

// smem layout (bytes) — score kernel
// X: 2 bufs x 32 KB partial-exchange planes (A prologue tile aliases X)
#define X_OFF    0
#define A_OFF    0                   // 256q x 128d fp16 = 65536 (prologue only)
#define B_OFF    65536               // 2 x (64 k x 128 d fp16) = 32768
#define SMEM_TOTAL 98304

// ---------------------------------------------------------------------------
// Scratch
// ---------------------------------------------------------------------------
__device__ float g_cval[BQ * CPQ];
__device__ int   g_cidx[BQ * CPQ];

// ---------------------------------------------------------------------------
// helpers
// ---------------------------------------------------------------------------
__device__ __forceinline__ uint32_t smem_u32(const void* p) {
    uint32_t a;
    asm("{ .reg .u64 t; cvta.to.shared.u64 t, %1; cvt.u32.u64 %0, t; }"
        : "=r"(a) : "l"(p));
    return a;
}
__device__ __forceinline__ void ldm_x4(uint32_t addr, uint32_t& r0, uint32_t& r1,
                                       uint32_t& r2, uint32_t& r3) {
    asm volatile("ldmatrix.sync.aligned.m8n8.x4.shared.b16 {%0,%1,%2,%3}, [%4];"
                 : "=r"(r0), "=r"(r1), "=r"(r2), "=r"(r3) : "r"(addr));
}
__device__ __forceinline__ void mma16816h(uint32_t& c0, uint32_t& c1,
                                          uint32_t a0, uint32_t a1, uint32_t a2, uint32_t a3,
                                          uint32_t b0, uint32_t b1) {
    asm volatile(
        "mma.sync.aligned.m16n8k16.row.col.f16.f16.f16.f16 "
        "{%0,%1}, {%2,%3,%4,%5}, {%6,%7}, {%0,%1};"
        : "+r"(c0), "+r"(c1)
        : "r"(a0), "r"(a1), "r"(a2), "r"(a3), "r"(b0), "r"(b1));
}
__device__ __forceinline__ uint32_t hadd2u(uint32_t a, uint32_t b) {
    __half2 r = __hadd2(*(const __half2*)&a, *(const __half2*)&b);
    return *(const uint32_t*)&r;
}
__device__ __forceinline__ uint32_t hmax2u(uint32_t a, uint32_t b) {
    __half2 r = __hmax2(*(const __half2*)&a, *(const __half2*)&b);
    return *(const uint32_t*)&r;
}
// monotone fp16 -> u16 transform (order-preserving), vectorized on 2 halves
__device__ __forceinline__ uint32_t xf2(uint32_t v) {
    uint32_t s = (v & 0x80008000u) >> 15;        // 0/1 per half at bits 0,16
    return v ^ 0x80008000u ^ (s * 0x7FFFu);
}

// exchange-plane addressing: [buf][pair(wm)][lane row 128B][8 x 16B chunks,
// rotated by lane] — conflict-free STS.128/LDS.128 per 8-lane phase.
__device__ __forceinline__ uint32_t x_addr(uint32_t sb, int buf, int pair,
                                           int lane, int j) {
    return sb + X_OFF + buf * 32768 + pair * 4096 + lane * 128 +
           (((j + lane) & 7) << 4);
}

__device__ __forceinline__ bool better(float v1, int i1, float v2, int i2) {
    return (v1 > v2) || (v1 == v2 && i1 < i2);
}

// ---------------------------------------------------------------------------
// MMA for one 64-key tile on this warp's D-half (32 rows x 64 cols)
// ---------------------------------------------------------------------------
__device__ __forceinline__ void mma_tile(uint32_t acc[2][8][2],
                                         const uint32_t afrag[4][2][4],
                                         const uint32_t bBase[4],
                                         uint32_t bufOff) {
    #pragma unroll
    for (int mb = 0; mb < 2; ++mb)
        #pragma unroll
        for (int nb = 0; nb < 8; ++nb) { acc[mb][nb][0] = 0u; acc[mb][nb][1] = 0u; }
    #pragma unroll
    for (int ks = 0; ks < 4; ++ks) {
        uint32_t b[4][4];
        #pragma unroll
        for (int nbp = 0; nbp < 4; ++nbp)
            ldm_x4((bBase[nbp] + bufOff) ^ (ks * 32),
                   b[nbp][0], b[nbp][1], b[nbp][2], b[nbp][3]);
        #pragma unroll
        for (int mb = 0; mb < 2; ++mb)
            #pragma unroll
            for (int nbp = 0; nbp < 4; ++nbp) {
                mma16816h(acc[mb][nbp * 2][0], acc[mb][nbp * 2][1],
                          afrag[ks][mb][0], afrag[ks][mb][1],
                          afrag[ks][mb][2], afrag[ks][mb][3],
                          b[nbp][0], b[nbp][1]);
                mma16816h(acc[mb][nbp * 2 + 1][0], acc[mb][nbp * 2 + 1][1],
                          afrag[ks][mb][0], afrag[ks][mb][1],
                          afrag[ks][mb][2], afrag[ks][mb][3],
                          b[nbp][2], b[nbp][3]);
            }
    }
}

// ---------------------------------------------------------------------------
// kh0: combine partner partials from X[buf] into acc (fp16 add), then select
// top-4 per (row, 16-col lane slice) into packed u32 lists.
// packed = xf2(val)<<16 | (8191 - idx_in_chunk)  -> integer order == value
// desc, index asc.
// ---------------------------------------------------------------------------
__device__ __forceinline__ void combine_select(uint32_t acc[2][8][2],
                                               uint32_t topl[4][4],
                                               const char* smem, uint32_t sb,
                                               int buf, int wm, int lane, int c2,
                                               int t0, int tp, int N) {
    #pragma unroll
    for (int j = 0; j < 8; ++j) {
        uint4 x = *(const uint4*)(smem + (x_addr(sb, buf, wm, lane, j) - sb));
        int mb = j >> 2, nbp = j & 3;
        acc[mb][nbp * 2][0]     = hadd2u(acc[mb][nbp * 2][0], x.x);
        acc[mb][nbp * 2][1]     = hadd2u(acc[mb][nbp * 2][1], x.y);
        acc[mb][nbp * 2 + 1][0] = hadd2u(acc[mb][nbp * 2 + 1][0], x.z);
        acc[mb][nbp * 2 + 1][1] = hadd2u(acc[mb][nbp * 2 + 1][1], x.w);
    }
    const int kb = (t0 + tp) * KT;
    #pragma unroll
    for (int r = 0; r < 4; ++r) {
        const int mb = r >> 1, rh = r & 1;
        uint32_t m01 = hmax2u(acc[mb][0][rh], acc[mb][1][rh]);
        uint32_t m23 = hmax2u(acc[mb][2][rh], acc[mb][3][rh]);
        uint32_t m45 = hmax2u(acc[mb][4][rh], acc[mb][5][rh]);
        uint32_t m67 = hmax2u(acc[mb][6][rh], acc[mb][7][rh]);
        uint32_t mm = hmax2u(hmax2u(m01, m23), hmax2u(m45, m67));
        __half2 mh = *(const __half2*)&mm;
        __half rowmax = __hmax(__low2half(mh), __high2half(mh));
        uint32_t k3 = topl[r][3] >> 16;
        uint32_t thrh = (k3 & 0x8000u) ? (k3 & 0x7FFFu) : ((~k3) & 0xFFFFu);
        if (__hge(rowmax, __ushort_as_half((unsigned short)thrh))) {
            uint32_t thr2 = (k3 << 16) | k3;
            uint32_t tv[8];
            uint32_t mask = 0;
            #pragma unroll
            for (int nb = 0; nb < 8; ++nb) {
                tv[nb] = xf2(acc[mb][nb][rh]);
                uint32_t ge = __vcmpgeu2(tv[nb], thr2);
                mask |= ((ge & 1u) | ((ge >> 15) & 2u)) << (nb * 2);
            }
            while (mask) {
                int bbit = __ffs(mask) - 1;
                mask &= mask - 1;
                int nb = bbit >> 1, hf = bbit & 1;
                int col = nb * 8 + c2 + hf;
                int gi = kb + col;
                if (gi >= N) continue;
                uint32_t v16 = (tv[nb] >> (hf * 16)) & 0xFFFFu;
                uint32_t pk = (v16 << 16) |
                              (8191u - (uint32_t)(tp * 64 + col));
                if (pk > topl[r][3]) {
                    topl[r][3] = pk;
                    #pragma unroll
                    for (int m2 = 3; m2 > 0; --m2) {
                        if (topl[r][m2] > topl[r][m2 - 1]) {
                            uint32_t tt = topl[r][m2];
                            topl[r][m2] = topl[r][m2 - 1];
                            topl[r][m2 - 1] = tt;
                        }
                    }
                }
            }
        }
    }
}

// ---------------------------------------------------------------------------
// Kernel 1: fused normalize + fp16 HMMA (K-split, A persistent in regs),
// in-register top-4-per-lane-slice selection (no score-plane round trip).
// grid (74, 2), block 512 (16 warps: 8 in M x 2 in K-split)
// ---------------------------------------------------------------------------
extern "C" __global__ void __launch_bounds__(THREADS, 1)
score_topk_kernel(const float* __restrict__ queries,
                  const float* __restrict__ keys, int N) {
    extern __shared__ __align__(1024) char smem[];
    const uint32_t sb = smem_u32(smem);

    const int tid  = threadIdx.x;
    const int lane = tid & 31;
    const int wid  = tid >> 5;
    const int wm   = wid >> 1;      // 0..7 : rows wm*32 .. +31
    const int kh   = wid & 1;       // 0..1 : D-half
    const int chunk = blockIdx.x;
    const int qhalf = blockIdx.y;

    const int ntTotal = (N + KT - 1) / KT;
    const int TPC     = (ntTotal + NCHUNK - 1) / NCHUNK;
    const int t0      = chunk * TPC;
    const int nt      = min(TPC, ntTotal - t0);

    // ---- prologue: normalize queries + fp16 A tile (aliases X planes) ----
    {
        int row = tid >> 1, half = tid & 1;
        const float4* src =
            (const float4*)&queries[(size_t)(qhalf * 256 + row) * D] + half * 16;
        float ss = 0.f;
        #pragma unroll
        for (int j = 0; j < 16; ++j) {
            float4 v = src[j];
            ss += v.x * v.x + v.y * v.y + v.z * v.z + v.w * v.w;
        }
        ss += __shfl_xor_sync(0xffffffffu, ss, 1);
        float scale = INV_TEMP / fmaxf(sqrtf(ss), EPS_F);
        #pragma unroll
        for (int j = 0; j < 8; ++j) {
            float4 f0 = src[j * 2], f1 = src[j * 2 + 1];
            __half2 h0 = __float22half2_rn(make_float2(f0.x * scale, f0.y * scale));
            __half2 h1 = __float22half2_rn(make_float2(f0.z * scale, f0.w * scale));
            __half2 h2 = __float22half2_rn(make_float2(f1.x * scale, f1.y * scale));
            __half2 h3 = __float22half2_rn(make_float2(f1.z * scale, f1.w * scale));
            uint4 pack = make_uint4(*(uint32_t*)&h0, *(uint32_t*)&h1,
                                    *(uint32_t*)&h2, *(uint32_t*)&h3);
            int c16 = half * 8 + j;
            int off = row * 256 + ((c16 * 16) ^ ((row & 7) << 4));
            *(uint4*)(smem + A_OFF + off) = pack;
        }
    }

    // key-loader identity (all threads): key kn = tid>>3, 16 dims at c16k
    const int kn = tid >> 3;
    const int c16k = tid & 7;
    float4 kr0, kr1, kr2, kr3;

    #define LDG_TILE(t_) do {                                                   \
        int gk = (t0 + (t_)) * KT + kn;                                         \
        if (gk < N) {                                                           \
            const float4* src = (const float4*)(keys + (size_t)gk * D) + c16k * 4; \
            kr0 = src[0]; kr1 = src[1]; kr2 = src[2]; kr3 = src[3];             \
        } else {                                                                \
            kr0 = kr1 = kr2 = kr3 = make_float4(0.f, 0.f, 0.f, 0.f);            \
        }                                                                       \
    } while (0)

    #define CONVERT_TO(buf_) do {                                               \
        __half2 h0 = __float22half2_rn(make_float2(kr0.x, kr0.y));              \
        __half2 h1 = __float22half2_rn(make_float2(kr0.z, kr0.w));              \
        __half2 h2 = __float22half2_rn(make_float2(kr1.x, kr1.y));              \
        __half2 h3 = __float22half2_rn(make_float2(kr1.z, kr1.w));              \
        uint4 p0 = make_uint4(*(uint32_t*)&h0, *(uint32_t*)&h1,                 \
                              *(uint32_t*)&h2, *(uint32_t*)&h3);                \
        int off0 = kn * 256 + (((c16k * 2 + 0) * 16) ^ ((kn & 7) << 4));        \
        *(uint4*)(smem + B_OFF + (buf_) * 16384 + off0) = p0;                   \
        __half2 h4 = __float22half2_rn(make_float2(kr2.x, kr2.y));              \
        __half2 h5 = __float22half2_rn(make_float2(kr2.z, kr2.w));              \
        __half2 h6 = __float22half2_rn(make_float2(kr3.x, kr3.y));              \
        __half2 h7 = __float22half2_rn(make_float2(kr3.z, kr3.w));              \
        uint4 p1 = make_uint4(*(uint32_t*)&h4, *(uint32_t*)&h5,                 \
                              *(uint32_t*)&h6, *(uint32_t*)&h7);                \
        int off1 = kn * 256 + (((c16k * 2 + 1) * 16) ^ ((kn & 7) << 4));        \
        *(uint4*)(smem + B_OFF + (buf_) * 16384 + off1) = p1;                   \
    } while (0)

    LDG_TILE(0);
    CONVERT_TO(0);
    if (nt > 1) LDG_TILE(1);
    __syncthreads();

    // ---- persistent A fragments for this D-half ----
    uint32_t afrag[4][2][4];
    #pragma unroll
    for (int mb = 0; mb < 2; ++mb) {
        int row = wm * 32 + mb * 16 + (lane & 15);
        uint32_t base = sb + A_OFF + row * 256 +
                        (((lane >> 4) * 16) ^ ((row & 7) << 4)) + kh * 128;
        #pragma unroll
        for (int ks = 0; ks < 4; ++ks)
            ldm_x4(base ^ (ks * 32), afrag[ks][mb][0], afrag[ks][mb][1],
                   afrag[ks][mb][2], afrag[ks][mb][3]);
    }
    __syncthreads();   // A (aliased by X) fully consumed

    uint32_t bBase[4];
    #pragma unroll
    for (int nbp = 0; nbp < 4; ++nbp) {
        int key = nbp * 16 + (lane & 7) + ((lane >> 4) << 3);
        uint32_t cb16 = (lane >> 3) & 1;
        bBase[nbp] = sb + B_OFF + key * 256 +
                     ((cb16 * 16) ^ ((key & 7) << 4)) + kh * 128;
    }

    uint32_t acc[2][8][2];
    const int c2 = (lane & 3) * 2;

    // packed top-4 lists: 4 rows (mb,rh) x 4 entries
    // init: -inf fp16 (0xFC00) -> transformed 0x03FF
    uint32_t topl[4][4];
    #pragma unroll
    for (int r = 0; r < 4; ++r)
        #pragma unroll
        for (int i = 0; i < 4; ++i) topl[r][i] = 0x03FF0000u;

    for (int t = 0; t < nt; ++t) {
        if (kh == 0) {
            if (t > 0)
                combine_select(acc, topl, smem, sb, (t - 1) & 1, wm, lane, c2,
                               t0, t - 1, N);
            mma_tile(acc, afrag, bBase, (uint32_t)(t & 1) * 16384);
            if (t + 1 < nt) {
                CONVERT_TO((t + 1) & 1);
                if (t + 2 < nt) LDG_TILE(t + 2);
            }
        } else {
            mma_tile(acc, afrag, bBase, (uint32_t)(t & 1) * 16384);
            // STS partials -> X[t&1] (conflict-free rotated STS.128)
            #pragma unroll
            for (int j = 0; j < 8; ++j) {
                int mb = j >> 2, nbp = j & 3;
                uint4 v = make_uint4(acc[mb][nbp * 2][0], acc[mb][nbp * 2][1],
                                     acc[mb][nbp * 2 + 1][0], acc[mb][nbp * 2 + 1][1]);
                *(uint4*)(smem + (x_addr(sb, t & 1, wm, lane, j) - sb)) = v;
            }
            if (t + 1 < nt) {
                CONVERT_TO((t + 1) & 1);
                if (t + 2 < nt) LDG_TILE(t + 2);
            }
        }
        __syncthreads();
    }

    // ---- tail: combine + select last tile; write candidates ----
    if (kh == 0) {
        combine_select(acc, topl, smem, sb, (nt - 1) & 1, wm, lane, c2,
                       t0, nt - 1, N);

        // 16 candidates per (query, chunk) = 4 lanes x top-4
        #pragma unroll
        for (int r = 0; r < 4; ++r) {
            int qrow = qhalf * 256 + wm * 32 + (r >> 1) * 16 + (lane >> 2) + (r & 1) * 8;
            long long base = ((long long)qrow * NCHUNK + chunk) * 16 + (lane & 3) * 4;
            #pragma unroll
            for (int i = 0; i < 4; ++i) {
                uint32_t pk = topl[r][i];
                uint32_t k = pk >> 16;
                uint32_t h = (k & 0x8000u) ? (k & 0x7FFFu) : ((~k) & 0xFFFFu);
                float val = __half2float(__ushort_as_half((unsigned short)h));
                int gi = t0 * KT + (int)(8191u - (pk & 0x1FFFu));
                if (gi >= N) { val = NEG_INF; gi = 0; }
                g_cval[base + i] = val;
                g_cidx[base + i] = gi;
            }
        }
    }
    #undef LDG_TILE
    #undef CONVERT_TO
}

// ---------------------------------------------------------------------------
// Kernel 2: warp-parallel merge (148 cands/warp) -> per-warp top-16 ->
//           exact fp32 rescore of 128 -> top-16 -> softmax -> gather
// ---------------------------------------------------------------------------
extern "C" __global__ void __launch_bounds__(256)
merge_kernel(const float* __restrict__ queries, const float* __restrict__ keys,
             const float* __restrict__ values, float* __restrict__ out,
             int Bn, int out_mode) {
    __shared__ float sv[CPQ];
    __shared__ int   si[CPQ];
    __shared__ float qsm[D];
    __shared__ int   selI[NRS];
    __shared__ float rsV[NRS];
    __shared__ float topv[TOPK]; __shared__ int topi[TOPK]; __shared__ float tw[TOPK];

    const int q = blockIdx.x, tid = threadIdx.x;
    const int wid = tid >> 5, lane = tid & 31;
    const long long cb = (long long)q * CPQ;

    for (int i = tid; i < CPQ; i += 256) { sv[i] = g_cval[cb + i]; si[i] = g_cidx[cb + i]; }
    if (wid == 0) {
        float4 v = *(const float4*)&queries[(size_t)q * D + lane * 4];
        float ss = v.x * v.x + v.y * v.y + v.z * v.z + v.w * v.w;
        #pragma unroll
        for (int o = 16; o > 0; o >>= 1) ss += __shfl_xor_sync(0xffffffffu, ss, o);
        float scale = INV_TEMP / fmaxf(sqrtf(ss), EPS_F);
        *(float4*)&qsm[lane * 4] = make_float4(v.x * scale, v.y * scale,
                                               v.z * scale, v.w * scale);
    }
    __syncthreads();

    // phase 1: per-warp top-16 over its 148 candidates
    {
        const int base = wid * WCAND;
        for (int e = 0; e < 16; ++e) {
            float bv = NEG_INF; int bi = 0x7fffffff; int bp = -1;
            #pragma unroll
            for (int r = 0; r < 5; ++r) {
                int idx = r * 32 + lane;
                if (idx < WCAND) {
                    float v = sv[base + idx]; int ii = si[base + idx];
                    if (better(v, ii, bv, bi)) { bv = v; bi = ii; bp = base + idx; }
                }
            }
            #pragma unroll
            for (int o = 16; o > 0; o >>= 1) {
                float ov = __shfl_xor_sync(0xffffffffu, bv, o);
                int   oi = __shfl_xor_sync(0xffffffffu, bi, o);
                int   op = __shfl_xor_sync(0xffffffffu, bp, o);
                if (better(ov, oi, bv, bi)) { bv = ov; bi = oi; bp = op; }
            }
            if (lane == 0) { selI[wid * 16 + e] = bi; sv[bp] = NEG_INF; }
            __syncwarp();
        }
    }
    __syncthreads();

    // phase 2: exact fp32 rescore of all 128
    #pragma unroll
    for (int r = 0; r < 16; ++r) {
        int s = r * 8 + wid;
        int ki = selI[s];
        float4 kv = ((const float4*)(keys + (size_t)ki * D))[lane];
        float4 qv = ((const float4*)qsm)[lane];
        float p = kv.x * qv.x + kv.y * qv.y + kv.z * qv.z + kv.w * qv.w;
        #pragma unroll
        for (int o = 16; o > 0; o >>= 1) p += __shfl_xor_sync(0xffffffffu, p, o);
        if (lane == 0) rsV[s] = p;
    }
    __syncthreads();

    // phase 3: warp 0 extracts exact top-16 + softmax
    if (wid == 0) {
        for (int it = 0; it < TOPK; ++it) {
            float bv = NEG_INF; int bi = 0x7fffffff; int bp = -1;
            #pragma unroll
            for (int r = 0; r < 4; ++r) {
                int pos = r * 32 + lane;
                float v = rsV[pos]; int ii = selI[pos];
                if (better(v, ii, bv, bi)) { bv = v; bi = ii; bp = pos; }
            }
            #pragma unroll
            for (int o = 16; o > 0; o >>= 1) {
                float ov = __shfl_xor_sync(0xffffffffu, bv, o);
                int   oi = __shfl_xor_sync(0xffffffffu, bi, o);
                int   op = __shfl_xor_sync(0xffffffffu, bp, o);
                if (better(ov, oi, bv, bi)) { bv = ov; bi = oi; bp = op; }
            }
            if (lane == 0) { topv[it] = bv; topi[it] = bi; rsV[bp] = NEG_INF; }
            __syncwarp();
        }
        if (lane == 0) {
            float m = topv[0], sum = 0.f;
            #pragma unroll
            for (int k = 0; k < TOPK; ++k) { float e = expf(topv[k] - m); tw[k] = e; sum += e; }
            sum += EPS_F;
            #pragma unroll
            for (int k = 0; k < TOPK; ++k) tw[k] /= sum;
        }
    }
    __syncthreads();

    if (tid < VD) {
        float a = 0.f;
        #pragma unroll
        for (int k = 0; k < TOPK; ++k)
            a += tw[k] * values[(size_t)topi[k] * VD + tid];
        out[(size_t)q * VD + tid] = a;
    }
    if (out_mode) {
        if (tid >= 64 && tid < 64 + TOPK)
            out[(size_t)Bn * VD + (size_t)q * TOPK + (tid - 64)] = tw[tid - 64];
        if (tid >= 80 && tid < 80 + TOPK)
            out[(size_t)Bn * VD + (size_t)Bn * TOPK + (size_t)q * TOPK + (tid - 80)] =
                (float)topi[tid - 80];
    }
}

// ---------------------------------------------------------------------------
// pad kernel: keeps ncu's skip-5 capture aligned on score_topk_kernel
// ---------------------------------------------------------------------------
__global__ void pad_kernel() {}

// ---------------------------------------------------------------------------
// launch
// ---------------------------------------------------------------------------
extern "C" void kernel_launch(void* const* d_in, const int* in_sizes, int n_in,
                              void* d_out, int out_size) {
    const float* queries = (const float*)d_in[0];
    const float* keys    = (const float*)d_in[1];
    const float* values  = (const float*)d_in[2];
    int Bn = in_sizes[0] / D;   // 512
    int N  = in_sizes[1] / D;   // 500000

    cudaFuncSetAttribute(score_topk_kernel,
                         cudaFuncAttributeMaxDynamicSharedMemorySize, SMEM_TOTAL);
    dim3 grid(NCHUNK, Bn / 256);
    score_topk_kernel<<<grid, THREADS, SMEM_TOTAL>>>(queries, keys, N);

    int out_mode = (out_size >= Bn * (VD + 2 * TOPK)) ? 1 : 0;
    merge_kernel<<<Bn, 256>>>(queries, keys, values, (float*)d_out, Bn, out_mode);

    pad_kernel<<<1, 32>>>();
}